// round 10
// baseline (speedup 1.0000x reference)
#include <cuda_runtime.h>
#include <cstdint>

// Problem constants
#define B_  128
#define D_  128
#define T_  2048
#define C_  64
#define ND_ ((long long)(B_ * T_) * D_)     // 33.5M

// Tiling
#define CHUNK       256
#define NCHUNK_TOT  (T_ / CHUNK)            // 8
#define NCHUNKS_BLK 4
#define TSPLIT      (NCHUNK_TOT / NCHUNKS_BLK)  // 2
#define DG          32
#define NDGRP       (D_ / DG)               // 4
#define ST          (CHUNK + 1)             // odd stride: conflict-free both ways
#define THREADS     256
#define NCU_TOT     (B_ * NCHUNK_TOT)       // 1024
#define NBLK_MAIN   (B_ * NDGRP * TSPLIT)   // 1024

// ---------------- device scratch (no allocations allowed) ----------------
__device__ float          g_featsum[C_ * D_];
__device__ int            g_counts[C_];
__device__ float          g_sumsq;
__device__ unsigned short g_list[NCU_TOT * CHUNK];
__device__ unsigned short g_base[NCU_TOT * C_];
__device__ unsigned short g_cnt [NCU_TOT * C_];

// ---------------------------------------------------------------------------
// K1: bucket t-indices by class per (b, chunk). Warp-scan prefix. Zeroes
// g_featsum / g_counts / g_sumsq. Dtype detect branch-free (MLP 16).
// ---------------------------------------------------------------------------
__global__ void __launch_bounds__(THREADS)
cl_bucket_kernel(const void* __restrict__ label_raw) {
    const int cu  = blockIdx.x;
    const int b   = cu / NCHUNK_TOT;
    const int tc  = cu % NCHUNK_TOT;
    const int tid = threadIdx.x;

    __shared__ int           s_cnt[C_];
    __shared__ int           s_off[C_];
    __shared__ int           s_lab64;
    __shared__ unsigned char s_lab[CHUNK];

    if (cu < (C_ * D_) / THREADS)
        g_featsum[cu * THREADS + tid] = 0.0f;
    if (cu == 0) {
        if (tid < C_) g_counts[tid] = 0;
        if (tid == 0) g_sumsq = 0.0f;
    }
    if (tid < C_) s_cnt[tid] = 0;

    // int64 vs int32 detect: 16 INDEPENDENT loads (no serial LDG chain)
    if (tid == 0) {
        const long long* l = (const long long*)label_raw;
        long long bad = 0;
        #pragma unroll
        for (int i = 0; i < 16; i++) bad |= (l[i] >> 6);   // 0 iff 0<=v<64
        s_lab64 = (bad == 0);
    }
    __syncthreads();

    const int* __restrict__ lab32 = (const int*)label_raw;
    const int gi  = b * T_ + tc * CHUNK + tid;
    const int lab = s_lab64 ? lab32[2 * gi] : lab32[gi];
    s_lab[tid] = (unsigned char)lab;
    atomicAdd(&s_cnt[lab], 1);
    __syncthreads();

    // warp-scan exclusive prefix over 64 counters (lane i owns 2i, 2i+1)
    if (tid < 32) {
        const int c0 = s_cnt[2 * tid];
        const int c1 = s_cnt[2 * tid + 1];
        int scan = c0 + c1;
        #pragma unroll
        for (int o = 1; o < 32; o <<= 1) {
            int v = __shfl_up_sync(0xFFFFFFFFu, scan, o);
            if (tid >= o) scan += v;
        }
        const int excl = scan - (c0 + c1);
        s_off[2 * tid]     = excl;
        s_off[2 * tid + 1] = excl + c0;
        g_base[cu * C_ + 2 * tid]     = (unsigned short)excl;
        g_base[cu * C_ + 2 * tid + 1] = (unsigned short)(excl + c0);
        g_cnt [cu * C_ + 2 * tid]     = (unsigned short)c0;
        g_cnt [cu * C_ + 2 * tid + 1] = (unsigned short)c1;
    }
    __syncthreads();

    const int pos = atomicAdd(&s_off[s_lab[tid]], 1);
    g_list[cu * CHUNK + pos] = (unsigned short)tid;
}

// ---------------------------------------------------------------------------
// K2: streaming pass, occupancy-first (6 blocks/SM, no register pipeline,
// no spills). Per chunk: lists + tile loaded straight (unroll-8 keeps MLP 8),
// then conflict-free class-ordered gather. Cross-block overlap hides latency.
// ---------------------------------------------------------------------------
__global__ void __launch_bounds__(THREADS, 6)
cl_main_kernel(const float* __restrict__ feature) {
    const int bid  = blockIdx.x;
    const int ts   = bid % TSPLIT;
    const int dgrp = (bid / TSPLIT) % NDGRP;
    const int b    = bid / (TSPLIT * NDGRP);
    const int d0   = dgrp * DG;
    const int tid  = threadIdx.x;
    const int w    = tid >> 5;
    const int lane = tid & 31;

    __shared__ float          s_tile[DG * ST];   // 32 x 257
    __shared__ unsigned short s_list[CHUNK];
    __shared__ unsigned short s_base[C_];
    __shared__ unsigned short s_cnt[C_];
    __shared__ float          s_red[THREADS / 32];

    const float* __restrict__ fblk =
        feature + ((size_t)b * D_ + d0) * T_ + (size_t)ts * NCHUNKS_BLK * CHUNK;
    const int cu0 = b * NCHUNK_TOT + ts * NCHUNKS_BLK;

    float acc[8];
    #pragma unroll
    for (int i = 0; i < 8; i++) acc[i] = 0.0f;
    float sumsq   = 0.0f;
    int   cnt_acc = 0;
    const bool do_cnt = (dgrp == 0);
    const int  lrow   = lane * ST;

    for (int ch = 0; ch < NCHUNKS_BLK; ch++) {
        if (ch) __syncthreads();            // tile + lists free (prev gather done)

        // lists for this chunk (tiny; latency overlaps tile LDGs below)
        const int cu = cu0 + ch;
        s_list[tid] = g_list[cu * CHUNK + tid];
        if (tid < C_) {
            const unsigned short bs = g_base[cu * C_ + tid];
            const unsigned short cn = g_cnt [cu * C_ + tid];
            s_base[tid] = bs;
            s_cnt [tid] = cn;
            if (do_cnt) cnt_acc += (int)cn;
        }

        // tile load: coalesced along t, MLP 8, only ~8 live regs
        const float* __restrict__ fb = fblk + ch * CHUNK;
        #pragma unroll 8
        for (int dg = 0; dg < DG; dg++) {
            const float v = __ldg(&fb[dg * T_ + tid]);
            sumsq += v * v;
            s_tile[dg * ST + tid] = v;
        }
        __syncthreads();                    // tile + lists ready

        // gather: warp w owns classes {w, w+8, ..., w+56}; lane = d offset
        #pragma unroll
        for (int ci = 0; ci < 8; ci++) {
            const int c    = w + 8 * ci;
            const int cnt  = s_cnt[c];
            const int base = s_base[c];
            float a = acc[ci];
            int k = 0;
            for (; k + 4 <= cnt; k += 4) {
                const int t0 = s_list[base + k + 0];
                const int t1 = s_list[base + k + 1];
                const int t2 = s_list[base + k + 2];
                const int t3 = s_list[base + k + 3];
                a += s_tile[lrow + t0];
                a += s_tile[lrow + t1];
                a += s_tile[lrow + t2];
                a += s_tile[lrow + t3];
            }
            for (; k < cnt; k++)
                a += s_tile[lrow + s_list[base + k]];
            acc[ci] = a;
        }
    }

    // merge register accumulators -> global featsum
    #pragma unroll
    for (int ci = 0; ci < 8; ci++) {
        const int c = w + 8 * ci;
        atomicAdd(&g_featsum[c * D_ + d0 + lane], acc[ci]);
    }
    if (do_cnt && tid < C_) atomicAdd(&g_counts[tid], cnt_acc);

    // block-reduce sumsq
    #pragma unroll
    for (int o = 16; o > 0; o >>= 1)
        sumsq += __shfl_down_sync(0xFFFFFFFFu, sumsq, o);
    if (lane == 0) s_red[w] = sumsq;
    __syncthreads();
    if (tid == 0) {
        float s = 0.0f;
        #pragma unroll
        for (int i = 0; i < THREADS / 32; i++) s += s_red[i];
        atomicAdd(&g_sumsq, s);
    }
}

// ---------------------------------------------------------------------------
// K3: finalize.
//   difference[c,d] = cnt>0 ? centers - featsum/cnt : 0
//   loss = (sumsq + sum_c cnt*||ctr||^2 - 2*sum ctr.featsum) / (N*D)
// out[0] = loss, out[1..8192] = difference row-major [C][D].
// ---------------------------------------------------------------------------
__global__ void __launch_bounds__(1024)
cl_finalize_kernel(const float* __restrict__ centers,
                   float* __restrict__ out) {
    __shared__ float s_warp[32];
    const int tid = threadIdx.x;

    float local = 0.0f;
    #pragma unroll
    for (int i = tid; i < C_ * D_; i += 1024) {
        const int   c   = i >> 7;
        const float ctr = centers[i];
        const float fs  = g_featsum[i];
        const int   cnt = g_counts[c];
        out[1 + i] = (cnt > 0) ? (ctr - fs / (float)cnt) : 0.0f;
        local += (float)cnt * ctr * ctr - 2.0f * ctr * fs;
    }

    #pragma unroll
    for (int o = 16; o > 0; o >>= 1)
        local += __shfl_down_sync(0xFFFFFFFFu, local, o);
    if ((tid & 31) == 0) s_warp[tid >> 5] = local;
    __syncthreads();

    if (tid == 0) {
        float cross = 0.0f;
        #pragma unroll
        for (int i = 0; i < 32; i++) cross += s_warp[i];
        out[0] = (g_sumsq + cross) / (float)ND_;
    }
}

// ---------------------------------------------------------------------------
extern "C" void kernel_launch(void* const* d_in, const int* in_sizes, int n_in,
                              void* d_out, int out_size) {
    const float* feature = (const float*)d_in[0];
    const void*  label   = d_in[1];
    const float* centers = (const float*)d_in[2];
    float* out = (float*)d_out;

    cl_bucket_kernel<<<NCU_TOT, THREADS>>>(label);
    cl_main_kernel<<<NBLK_MAIN, THREADS>>>(feature);
    cl_finalize_kernel<<<1, 1024>>>(centers, out);
}

// round 11
// speedup vs baseline: 1.2895x; 1.2895x over previous
#include <cuda_runtime.h>
#include <cstdint>

// Problem constants
#define B_  128
#define D_  128
#define T_  2048
#define C_  64
#define ND_ ((long long)(B_ * T_) * D_)     // 33.5M

// Tiling (R5-proven K2 geometry)
#define CHUNK       256
#define NCHUNK_TOT  (T_ / CHUNK)            // 8
#define NCHUNKS_BLK 4
#define TSPLIT      (NCHUNK_TOT / NCHUNKS_BLK)  // 2
#define DG          32
#define NDGRP       (D_ / DG)               // 4
#define ST          (CHUNK + 1)             // odd stride: conflict-free both ways
#define THREADS     256
#define NCU_TOT     (B_ * NCHUNK_TOT)       // 1024
#define NBLK_MAIN   (B_ * NDGRP * TSPLIT)   // 1024
#define K1_UNITS    4                       // chunk-units per K1 block
#define K1_BLOCKS   (NCU_TOT / K1_UNITS)    // 256

// ---------------- device scratch (no allocations allowed) ----------------
__device__ float          g_featsum[C_ * D_];
__device__ int            g_counts[C_];
__device__ float          g_sumsq;
__device__ unsigned short g_list[NCU_TOT * CHUNK];
__device__ unsigned short g_base[NCU_TOT * C_];
__device__ unsigned short g_cnt [NCU_TOT * C_];

// ---------------------------------------------------------------------------
// K1: bucket t-indices by class. 256 blocks x 4 chunk-units each (amortizes
// per-block latency). Warp-scan prefix. Zeroes g_featsum/g_counts/g_sumsq.
// ---------------------------------------------------------------------------
__global__ void __launch_bounds__(THREADS)
cl_bucket_kernel(const void* __restrict__ label_raw) {
    const int tid = threadIdx.x;

    __shared__ int           s_cnt[C_];
    __shared__ int           s_off[C_];
    __shared__ int           s_lab64;
    __shared__ unsigned char s_lab[CHUNK];

    // distributed zeroing (blocks 0..31 cover the 8192-float featsum)
    if (blockIdx.x < (C_ * D_) / THREADS)
        g_featsum[blockIdx.x * THREADS + tid] = 0.0f;
    if (blockIdx.x == 0) {
        if (tid < C_) g_counts[tid] = 0;
        if (tid == 0) g_sumsq = 0.0f;
    }

    // label dtype detect (int64 vs int32): independent loads, MLP 16
    if (tid == 0) {
        const long long* l = (const long long*)label_raw;
        long long bad = 0;
        #pragma unroll
        for (int i = 0; i < 16; i++) bad |= (l[i] >> 6);   // 0 iff 0<=v<64
        s_lab64 = (bad == 0);
    }
    __syncthreads();
    const int lab64 = s_lab64;
    const int* __restrict__ lab32 = (const int*)label_raw;

    for (int u = 0; u < K1_UNITS; u++) {
        const int cu = blockIdx.x * K1_UNITS + u;

        if (u) __syncthreads();             // s_cnt/s_off reusable
        if (tid < C_) s_cnt[tid] = 0;
        __syncthreads();

        const int gi  = cu * CHUNK + tid;   // NCU_TOT*CHUNK == B_*T_ layout
        const int lab = lab64 ? lab32[2 * gi] : lab32[gi];
        s_lab[tid] = (unsigned char)lab;
        atomicAdd(&s_cnt[lab], 1);
        __syncthreads();

        // warp-scan exclusive prefix over 64 counters (lane i owns 2i, 2i+1)
        if (tid < 32) {
            const int c0 = s_cnt[2 * tid];
            const int c1 = s_cnt[2 * tid + 1];
            int scan = c0 + c1;
            #pragma unroll
            for (int o = 1; o < 32; o <<= 1) {
                int v = __shfl_up_sync(0xFFFFFFFFu, scan, o);
                if (tid >= o) scan += v;
            }
            const int excl = scan - (c0 + c1);
            s_off[2 * tid]     = excl;
            s_off[2 * tid + 1] = excl + c0;
            g_base[cu * C_ + 2 * tid]     = (unsigned short)excl;
            g_base[cu * C_ + 2 * tid + 1] = (unsigned short)(excl + c0);
            g_cnt [cu * C_ + 2 * tid]     = (unsigned short)c0;
            g_cnt [cu * C_ + 2 * tid + 1] = (unsigned short)c1;
        }
        __syncthreads();

        const int pos = atomicAdd(&s_off[s_lab[tid]], 1);
        g_list[cu * CHUNK + pos] = (unsigned short)tid;
    }
}

// ---------------------------------------------------------------------------
// K2: streaming pass — R5-proven register-pipelined structure, but with
// __launch_bounds__(256,3) (85-reg budget) so r[32]+acc[8] fit WITHOUT spills.
// ---------------------------------------------------------------------------
__global__ void __launch_bounds__(THREADS, 3)
cl_main_kernel(const float* __restrict__ feature) {
    const int bid  = blockIdx.x;
    const int ts   = bid % TSPLIT;
    const int dgrp = (bid / TSPLIT) % NDGRP;
    const int b    = bid / (TSPLIT * NDGRP);
    const int d0   = dgrp * DG;
    const int tid  = threadIdx.x;
    const int w    = tid >> 5;
    const int lane = tid & 31;

    __shared__ float          s_tile[DG * ST];
    __shared__ unsigned short s_list[CHUNK];
    __shared__ unsigned short s_base[C_];
    __shared__ unsigned short s_cnt[C_];
    __shared__ float          s_red[THREADS / 32];

    const float* __restrict__ fblk =
        feature + ((size_t)b * D_ + d0) * T_ + (size_t)ts * NCHUNKS_BLK * CHUNK;
    const int cu0 = b * NCHUNK_TOT + ts * NCHUNKS_BLK;

    float r[DG];
    unsigned short rlist = 0, rbase = 0, rcnt = 0;

    // prologue: prefetch chunk 0
    {
        const float* __restrict__ fb = fblk;
        #pragma unroll
        for (int dg = 0; dg < DG; dg++) r[dg] = __ldg(&fb[dg * T_ + tid]);
        rlist = g_list[cu0 * CHUNK + tid];
        if (tid < C_) {
            rbase = g_base[cu0 * C_ + tid];
            rcnt  = g_cnt [cu0 * C_ + tid];
        }
    }

    float acc[8];
    #pragma unroll
    for (int i = 0; i < 8; i++) acc[i] = 0.0f;
    float sumsq   = 0.0f;
    int   cnt_acc = 0;
    const bool do_cnt = (dgrp == 0);

    for (int ch = 0; ch < NCHUNKS_BLK; ch++) {
        if (ch) __syncthreads();            // tile free (prev gather done)

        // stage regs -> shared (conflict-free: stride-1 across lanes)
        #pragma unroll
        for (int dg = 0; dg < DG; dg++) {
            const float v = r[dg];
            sumsq += v * v;
            s_tile[dg * ST + tid] = v;
        }
        s_list[tid] = rlist;
        if (tid < C_) {
            s_base[tid] = rbase;
            s_cnt [tid] = rcnt;
            if (do_cnt) cnt_acc += (int)rcnt;
        }
        __syncthreads();                    // tile + lists ready

        // prefetch chunk ch+1 (independent of gather -> overlaps it)
        if (ch + 1 < NCHUNKS_BLK) {
            const float* __restrict__ fb = fblk + (ch + 1) * CHUNK;
            #pragma unroll
            for (int dg = 0; dg < DG; dg++) r[dg] = __ldg(&fb[dg * T_ + tid]);
            const int cu = cu0 + ch + 1;
            rlist = g_list[cu * CHUNK + tid];
            if (tid < C_) {
                rbase = g_base[cu * C_ + tid];
                rcnt  = g_cnt [cu * C_ + tid];
            }
        }

        // gather: warp w owns classes {w, w+8, ..., w+56}; lane = d offset
        #pragma unroll
        for (int ci = 0; ci < 8; ci++) {
            const int c    = w + 8 * ci;
            const int cnt  = s_cnt[c];
            const int base = s_base[c];
            float a = acc[ci];
            int k = 0;
            for (; k + 4 <= cnt; k += 4) {
                const int t0 = s_list[base + k + 0];
                const int t1 = s_list[base + k + 1];
                const int t2 = s_list[base + k + 2];
                const int t3 = s_list[base + k + 3];
                a += s_tile[lane * ST + t0];
                a += s_tile[lane * ST + t1];
                a += s_tile[lane * ST + t2];
                a += s_tile[lane * ST + t3];
            }
            for (; k < cnt; k++)
                a += s_tile[lane * ST + s_list[base + k]];
            acc[ci] = a;
        }
    }

    // merge register accumulators -> global featsum
    #pragma unroll
    for (int ci = 0; ci < 8; ci++) {
        const int c = w + 8 * ci;
        atomicAdd(&g_featsum[c * D_ + d0 + lane], acc[ci]);
    }
    if (do_cnt && tid < C_) atomicAdd(&g_counts[tid], cnt_acc);

    // block-reduce sumsq
    #pragma unroll
    for (int o = 16; o > 0; o >>= 1)
        sumsq += __shfl_down_sync(0xFFFFFFFFu, sumsq, o);
    if (lane == 0) s_red[w] = sumsq;
    __syncthreads();
    if (tid == 0) {
        float s = 0.0f;
        #pragma unroll
        for (int i = 0; i < THREADS / 32; i++) s += s_red[i];
        atomicAdd(&g_sumsq, s);
    }
}

// ---------------------------------------------------------------------------
// K3: finalize.
//   difference[c,d] = cnt>0 ? centers - featsum/cnt : 0
//   loss = (sumsq + sum_c cnt*||ctr||^2 - 2*sum ctr.featsum) / (N*D)
// out[0] = loss, out[1..8192] = difference row-major [C][D].
// ---------------------------------------------------------------------------
__global__ void __launch_bounds__(1024)
cl_finalize_kernel(const float* __restrict__ centers,
                   float* __restrict__ out) {
    __shared__ float s_warp[32];
    const int tid = threadIdx.x;

    float local = 0.0f;
    #pragma unroll
    for (int i = tid; i < C_ * D_; i += 1024) {
        const int   c   = i >> 7;
        const float ctr = centers[i];
        const float fs  = g_featsum[i];
        const int   cnt = g_counts[c];
        out[1 + i] = (cnt > 0) ? (ctr - fs / (float)cnt) : 0.0f;
        local += (float)cnt * ctr * ctr - 2.0f * ctr * fs;
    }

    #pragma unroll
    for (int o = 16; o > 0; o >>= 1)
        local += __shfl_down_sync(0xFFFFFFFFu, local, o);
    if ((tid & 31) == 0) s_warp[tid >> 5] = local;
    __syncthreads();

    if (tid == 0) {
        float cross = 0.0f;
        #pragma unroll
        for (int i = 0; i < 32; i++) cross += s_warp[i];
        out[0] = (g_sumsq + cross) / (float)ND_;
    }
}

// ---------------------------------------------------------------------------
extern "C" void kernel_launch(void* const* d_in, const int* in_sizes, int n_in,
                              void* d_out, int out_size) {
    const float* feature = (const float*)d_in[0];
    const void*  label   = d_in[1];
    const float* centers = (const float*)d_in[2];
    float* out = (float*)d_out;

    cl_bucket_kernel<<<K1_BLOCKS, THREADS>>>(label);
    cl_main_kernel<<<NBLK_MAIN, THREADS>>>(feature);
    cl_finalize_kernel<<<1, 1024>>>(centers, out);
}

// round 14
// speedup vs baseline: 1.5795x; 1.2249x over previous
#include <cuda_runtime.h>
#include <cstdint>

// Problem constants
#define B_  128
#define D_  128
#define T_  2048
#define C_  64
#define ND_ ((long long)(B_ * T_) * D_)     // 33.5M

// Tiling (R4-proven geometry)
#define CHUNK       256
#define NCHUNK_TOT  (T_ / CHUNK)            // 8
#define NCHUNKS_BLK 4
#define TSPLIT      (NCHUNK_TOT / NCHUNKS_BLK)  // 2
#define DG          32
#define HG          16                      // prefetched half of DG
#define NDGRP       (D_ / DG)               // 4
#define ST          (CHUNK + 1)             // odd stride: conflict-free both ways
#define THREADS     256
#define NCU_TOT     (B_ * NCHUNK_TOT)       // 1024
#define NBLK_MAIN   (B_ * NDGRP * TSPLIT)   // 1024

// ---------------- device scratch (no allocations allowed) ----------------
__device__ float          g_featsum[C_ * D_];
__device__ int            g_counts[C_];
__device__ float          g_sumsq;
__device__ unsigned short g_list[NCU_TOT * CHUNK];
__device__ unsigned short g_base[NCU_TOT * C_];
__device__ unsigned short g_cnt [NCU_TOT * C_];

// ---------------------------------------------------------------------------
// K1: bucket t-indices by class per (b, chunk) — 1024 blocks (best measured).
// Warp-scan prefix. Zeroes g_featsum / g_counts / g_sumsq.
// ---------------------------------------------------------------------------
__global__ void __launch_bounds__(THREADS)
cl_bucket_kernel(const void* __restrict__ label_raw) {
    const int cu  = blockIdx.x;
    const int tid = threadIdx.x;

    __shared__ int           s_cnt[C_];
    __shared__ int           s_off[C_];
    __shared__ int           s_lab64;
    __shared__ unsigned char s_lab[CHUNK];

    if (cu < (C_ * D_) / THREADS)
        g_featsum[cu * THREADS + tid] = 0.0f;
    if (cu == 0) {
        if (tid < C_) g_counts[tid] = 0;
        if (tid == 0) g_sumsq = 0.0f;
    }
    if (tid < C_) s_cnt[tid] = 0;

    // label dtype detect (int64 vs int32): independent loads, MLP 16
    if (tid == 0) {
        const long long* l = (const long long*)label_raw;
        long long bad = 0;
        #pragma unroll
        for (int i = 0; i < 16; i++) bad |= (l[i] >> 6);   // 0 iff 0<=v<64
        s_lab64 = (bad == 0);
    }
    __syncthreads();

    const int* __restrict__ lab32 = (const int*)label_raw;
    const int gi  = cu * CHUNK + tid;       // row-major over B*T
    const int lab = s_lab64 ? lab32[2 * gi] : lab32[gi];
    s_lab[tid] = (unsigned char)lab;
    atomicAdd(&s_cnt[lab], 1);
    __syncthreads();

    // warp-scan exclusive prefix over 64 counters (lane i owns 2i, 2i+1)
    if (tid < 32) {
        const int c0 = s_cnt[2 * tid];
        const int c1 = s_cnt[2 * tid + 1];
        int scan = c0 + c1;
        #pragma unroll
        for (int o = 1; o < 32; o <<= 1) {
            int v = __shfl_up_sync(0xFFFFFFFFu, scan, o);
            if (tid >= o) scan += v;
        }
        const int excl = scan - (c0 + c1);
        s_off[2 * tid]     = excl;
        s_off[2 * tid + 1] = excl + c0;
        g_base[cu * C_ + 2 * tid]     = (unsigned short)excl;
        g_base[cu * C_ + 2 * tid + 1] = (unsigned short)(excl + c0);
        g_cnt [cu * C_ + 2 * tid]     = (unsigned short)c0;
        g_cnt [cu * C_ + 2 * tid + 1] = (unsigned short)c1;
    }
    __syncthreads();

    const int pos = atomicAdd(&s_off[s_lab[tid]], 1);
    g_list[cu * CHUNK + pos] = (unsigned short)tid;
}

// ---------------------------------------------------------------------------
// K2: streaming pass. Half-prefetch pipeline: r[16] carries d 0..15 of the
// next chunk across the gather (latency hidden); d 16..31 load at stage time
// through short-lived tmp regs (MLP 16). Peak live regs ~50 -> occ 4, NO
// spills. Conflict-free stride-257 tile, zero atomics in hot path.
// ---------------------------------------------------------------------------
__global__ void __launch_bounds__(THREADS, 4)
cl_main_kernel(const float* __restrict__ feature) {
    const int bid  = blockIdx.x;
    const int ts   = bid % TSPLIT;
    const int dgrp = (bid / TSPLIT) % NDGRP;
    const int b    = bid / (TSPLIT * NDGRP);
    const int d0   = dgrp * DG;
    const int tid  = threadIdx.x;
    const int w    = tid >> 5;
    const int lane = tid & 31;

    __shared__ float          s_tile[DG * ST];
    __shared__ unsigned short s_list[CHUNK];
    __shared__ unsigned short s_base[C_];
    __shared__ unsigned short s_cnt[C_];
    __shared__ float          s_red[THREADS / 32];

    const float* __restrict__ fblk =
        feature + ((size_t)b * D_ + d0) * T_ + (size_t)ts * NCHUNKS_BLK * CHUNK;
    const int cu0 = b * NCHUNK_TOT + ts * NCHUNKS_BLK;

    float r[HG];
    unsigned short rlist = 0, rbase = 0, rcnt = 0;

    // prologue: prefetch first half of chunk 0 + its metadata
    {
        const float* __restrict__ fb = fblk;
        #pragma unroll
        for (int dg = 0; dg < HG; dg++) r[dg] = __ldg(&fb[dg * T_ + tid]);
        rlist = g_list[cu0 * CHUNK + tid];
        if (tid < C_) {
            rbase = g_base[cu0 * C_ + tid];
            rcnt  = g_cnt [cu0 * C_ + tid];
        }
    }

    float acc[8];
    #pragma unroll
    for (int i = 0; i < 8; i++) acc[i] = 0.0f;
    float sumsq   = 0.0f;
    int   cnt_acc = 0;
    const bool do_cnt = (dgrp == 0);

    for (int ch = 0; ch < NCHUNKS_BLK; ch++) {
        if (ch) __syncthreads();            // tile free (prev gather done)

        const float* __restrict__ fb = fblk + ch * CHUNK;

        // stage prefetched first half (d 0..15)
        #pragma unroll
        for (int dg = 0; dg < HG; dg++) {
            const float v = r[dg];
            sumsq += v * v;
            s_tile[dg * ST + tid] = v;
        }
        // second half (d 16..31): short-lived tmp regs, MLP 16, one stall
        {
            float tmp[HG];
            #pragma unroll
            for (int j = 0; j < HG; j++)
                tmp[j] = __ldg(&fb[(HG + j) * T_ + tid]);
            #pragma unroll
            for (int j = 0; j < HG; j++) {
                const float v = tmp[j];
                sumsq += v * v;
                s_tile[(HG + j) * ST + tid] = v;
            }
        }
        s_list[tid] = rlist;
        if (tid < C_) {
            s_base[tid] = rbase;
            s_cnt [tid] = rcnt;
            if (do_cnt) cnt_acc += (int)rcnt;
        }
        __syncthreads();                    // tile + lists ready

        // prefetch next chunk's first half + metadata (overlaps gather)
        if (ch + 1 < NCHUNKS_BLK) {
            const float* __restrict__ fn = fblk + (ch + 1) * CHUNK;
            #pragma unroll
            for (int dg = 0; dg < HG; dg++) r[dg] = __ldg(&fn[dg * T_ + tid]);
            const int cu = cu0 + ch + 1;
            rlist = g_list[cu * CHUNK + tid];
            if (tid < C_) {
                rbase = g_base[cu * C_ + tid];
                rcnt  = g_cnt [cu * C_ + tid];
            }
        }

        // gather: warp w owns classes {w, w+8, ..., w+56}; lane = d offset
        #pragma unroll
        for (int ci = 0; ci < 8; ci++) {
            const int c    = w + 8 * ci;
            const int cnt  = s_cnt[c];
            const int base = s_base[c];
            float a = acc[ci];
            int k = 0;
            for (; k + 4 <= cnt; k += 4) {
                const int t0 = s_list[base + k + 0];
                const int t1 = s_list[base + k + 1];
                const int t2 = s_list[base + k + 2];
                const int t3 = s_list[base + k + 3];
                a += s_tile[lane * ST + t0];
                a += s_tile[lane * ST + t1];
                a += s_tile[lane * ST + t2];
                a += s_tile[lane * ST + t3];
            }
            for (; k < cnt; k++)
                a += s_tile[lane * ST + s_list[base + k]];
            acc[ci] = a;
        }
    }

    // merge register accumulators -> global featsum
    #pragma unroll
    for (int ci = 0; ci < 8; ci++) {
        const int c = w + 8 * ci;
        atomicAdd(&g_featsum[c * D_ + d0 + lane], acc[ci]);
    }
    if (do_cnt && tid < C_) atomicAdd(&g_counts[tid], cnt_acc);

    // block-reduce sumsq
    #pragma unroll
    for (int o = 16; o > 0; o >>= 1)
        sumsq += __shfl_down_sync(0xFFFFFFFFu, sumsq, o);
    if (lane == 0) s_red[w] = sumsq;
    __syncthreads();
    if (tid == 0) {
        float s = 0.0f;
        #pragma unroll
        for (int i = 0; i < THREADS / 32; i++) s += s_red[i];
        atomicAdd(&g_sumsq, s);
    }
}

// ---------------------------------------------------------------------------
// K3: finalize.
//   difference[c,d] = cnt>0 ? centers - featsum/cnt : 0
//   loss = (sumsq + sum_c cnt*||ctr||^2 - 2*sum ctr.featsum) / (N*D)
// out[0] = loss, out[1..8192] = difference row-major [C][D].
// ---------------------------------------------------------------------------
__global__ void __launch_bounds__(1024)
cl_finalize_kernel(const float* __restrict__ centers,
                   float* __restrict__ out) {
    __shared__ float s_warp[32];
    const int tid = threadIdx.x;

    float local = 0.0f;
    #pragma unroll
    for (int i = tid; i < C_ * D_; i += 1024) {
        const int   c   = i >> 7;
        const float ctr = centers[i];
        const float fs  = g_featsum[i];
        const int   cnt = g_counts[c];
        out[1 + i] = (cnt > 0) ? (ctr - fs / (float)cnt) : 0.0f;
        local += (float)cnt * ctr * ctr - 2.0f * ctr * fs;
    }

    #pragma unroll
    for (int o = 16; o > 0; o >>= 1)
        local += __shfl_down_sync(0xFFFFFFFFu, local, o);
    if ((tid & 31) == 0) s_warp[tid >> 5] = local;
    __syncthreads();

    if (tid == 0) {
        float cross = 0.0f;
        #pragma unroll
        for (int i = 0; i < 32; i++) cross += s_warp[i];
        out[0] = (g_sumsq + cross) / (float)ND_;
    }
}

// ---------------------------------------------------------------------------
extern "C" void kernel_launch(void* const* d_in, const int* in_sizes, int n_in,
                              void* d_out, int out_size) {
    const float* feature = (const float*)d_in[0];
    const void*  label   = d_in[1];
    const float* centers = (const float*)d_in[2];
    float* out = (float*)d_out;

    cl_bucket_kernel<<<NCU_TOT, THREADS>>>(label);
    cl_main_kernel<<<NBLK_MAIN, THREADS>>>(feature);
    cl_finalize_kernel<<<1, 1024>>>(centers, out);
}